// round 16
// baseline (speedup 1.0000x reference)
#include <cuda_runtime.h>
#include <cuda_bf16.h>

#define IMAGE 224
#define PAD   30
#define CROP  (IMAGE - 2 * PAD)   // 164
#define NB    16
#define NT    16
#define W8    (IMAGE / 8)         // 28

// 256-bit global load/store (sm_100+ / sm_103a). Volatile keeps relative
// order so the 4 loads of a batch issue back-to-back (MLP >= 4 per thread,
// 32B each = 128B outstanding per thread per batch).
#define LDG256(v, ptr)                                                      \
    asm volatile("ld.global.v8.f32 {%0,%1,%2,%3,%4,%5,%6,%7}, [%8];"        \
        : "=f"((v)[0]), "=f"((v)[1]), "=f"((v)[2]), "=f"((v)[3]),           \
          "=f"((v)[4]), "=f"((v)[5]), "=f"((v)[6]), "=f"((v)[7])            \
        : "l"(ptr))

#define STG256(ptr, v)                                                      \
    asm volatile("st.global.v8.f32 [%0], {%1,%2,%3,%4,%5,%6,%7,%8};"        \
        :: "l"(ptr),                                                        \
           "f"((v)[0]), "f"((v)[1]), "f"((v)[2]), "f"((v)[3]),              \
           "f"((v)[4]), "f"((v)[5]), "f"((v)[6]), "f"((v)[7])               \
        : "memory")

__global__ __launch_bounds__(256) void prompt_add_kernel(
    const float* __restrict__ x,
    const float* __restrict__ pu1,  const float* __restrict__ pu10,
    const float* __restrict__ pd1,  const float* __restrict__ pd10,
    const float* __restrict__ pl1,  const float* __restrict__ pl10,
    const float* __restrict__ pr1,  const float* __restrict__ pr10,
    const int*   __restrict__ cam_idx,
    const int*   __restrict__ off_right,
    const int*   __restrict__ off_down,
    float* __restrict__ out)
{
    const int idx = blockIdx.x * blockDim.x + threadIdx.x;
    // grid is exact: NB*3*IMAGE*W8 = 301056 = 1176 * 256

    const int w8 = idx % W8;
    const int h  = (idx / W8) % IMAGE;
    const int c  = (idx / (W8 * IMAGE)) % 3;
    const int b  =  idx / (W8 * IMAGE * 3);

    const int ci  = cam_idx[b];
    const int orr = off_right[b];   // in [1, 30]
    const int od  = off_down[b];    // in [1, 30]

    const int off_l = 2 * PAD - orr;     // [30, 59]
    const int off_u = 2 * PAD - od;      // [30, 59]
    const int n10_l = off_l / 10;
    const int n10_u = off_u / 10;
    const int n1_r  = orr % 10;
    const int n1_d  = od % 10;

    int r = h - off_u;
    r = r < 0 ? 0 : (r > CROP - 1 ? CROP - 1 : r);
    const int hd = h - (IMAGE - od);

    // per-(ci, c) pad table bases (tiny, L1/L2 resident)
    const float* PU1  = pu1  + (ci * 3 + c) * IMAGE;       // [224]
    const float* PU10 = pu10 + (ci * 3 + c) * 10 * IMAGE;  // [10,224]
    const float* PD1  = pd1  + (ci * 3 + c) * IMAGE;
    const float* PD10 = pd10 + (ci * 3 + c) * 10 * IMAGE;
    const float* PL1  = pl1  + (ci * 3 + c) * CROP;        // [164]
    const float* PL10 = pl10 + (ci * 3 + c) * CROP * 10;   // [164,10]
    const float* PR1  = pr1  + (ci * 3 + c) * CROP;
    const float* PR10 = pr10 + (ci * 3 + c) * CROP * 10;

    // ------- build the 8 prompt scalars for this w-span -------
    float p[8];
    #pragma unroll
    for (int k = 0; k < 8; k++) {
        const int w = w8 * 8 + k;
        float v;
        if (h < off_u) {
            v = (h < n10_u * 10) ? __ldg(&PU10[(h % 10) * IMAGE + w])
                                 : __ldg(&PU1[w]);
        } else if (h >= IMAGE - od) {
            if (hd < n1_d) {
                v = __ldg(&PD1[w]);
            } else {
                const int di = (hd - n1_d) % 10;
                v = __ldg(&PD10[di * IMAGE + w]);
            }
        } else {
            if (w < off_l) {
                v = (w < n10_l * 10) ? __ldg(&PL10[r * 10 + (w % 10)])
                                     : __ldg(&PL1[r]);
            } else if (w >= IMAGE - orr) {
                const int wd = w - (IMAGE - orr);
                if (wd < n1_r) {
                    v = __ldg(&PR1[r]);
                } else {
                    const int ri = (wd - n1_r) % 10;
                    v = __ldg(&PR10[r * 10 + ri]);
                }
            } else {
                v = 0.0f;
            }
        }
        p[k] = v;
    }

    // ------- stream x across T with 256-bit accesses, 4-deep batches -------
    const size_t plane = (size_t)IMAGE * IMAGE;                 // 50176 floats
    const size_t base  = ((size_t)(b * 3 + c) * NT) * plane
                       + (size_t)h * IMAGE + (size_t)w8 * 8;
    const float* __restrict__ xin  = x   + base;
    float*       __restrict__ xout = out + base;

    #pragma unroll
    for (int tb = 0; tb < NT; tb += 4) {
        float v0[8], v1[8], v2[8], v3[8];
        // 4 independent 32B loads back-to-back
        LDG256(v0, xin + (size_t)(tb + 0) * plane);
        LDG256(v1, xin + (size_t)(tb + 1) * plane);
        LDG256(v2, xin + (size_t)(tb + 2) * plane);
        LDG256(v3, xin + (size_t)(tb + 3) * plane);

        #pragma unroll
        for (int k = 0; k < 8; k++) {
            v0[k] += p[k];
            v1[k] += p[k];
            v2[k] += p[k];
            v3[k] += p[k];
        }

        STG256(xout + (size_t)(tb + 0) * plane, v0);
        STG256(xout + (size_t)(tb + 1) * plane, v1);
        STG256(xout + (size_t)(tb + 2) * plane, v2);
        STG256(xout + (size_t)(tb + 3) * plane, v3);
    }
}

extern "C" void kernel_launch(void* const* d_in, const int* in_sizes, int n_in,
                              void* d_out, int out_size) {
    const float* x    = (const float*)d_in[0];
    const float* pu1  = (const float*)d_in[1];
    const float* pu10 = (const float*)d_in[2];
    const float* pd1  = (const float*)d_in[3];
    const float* pd10 = (const float*)d_in[4];
    const float* pl1  = (const float*)d_in[5];
    const float* pl10 = (const float*)d_in[6];
    const float* pr1  = (const float*)d_in[7];
    const float* pr10 = (const float*)d_in[8];
    const int* cam_idx   = (const int*)d_in[9];
    const int* off_right = (const int*)d_in[10];
    const int* off_down  = (const int*)d_in[11];
    float* out = (float*)d_out;

    const int total   = NB * 3 * IMAGE * W8;   // 301056
    const int threads = 256;
    const int blocks  = total / threads;       // 1176 exact

    prompt_add_kernel<<<blocks, threads>>>(
        x, pu1, pu10, pd1, pd10, pl1, pl10, pr1, pr10,
        cam_idx, off_right, off_down, out);
}

// round 17
// speedup vs baseline: 1.0442x; 1.0442x over previous
#include <cuda_runtime.h>
#include <cuda_bf16.h>

#define IMAGE 224
#define PAD   30
#define CROP  (IMAGE - 2 * PAD)   // 164
#define NB    16
#define NT    16
#define W4    (IMAGE / 4)         // 56

__global__ __launch_bounds__(256) void prompt_add_kernel(
    const float* __restrict__ x,
    const float* __restrict__ pu1,  const float* __restrict__ pu10,
    const float* __restrict__ pd1,  const float* __restrict__ pd10,
    const float* __restrict__ pl1,  const float* __restrict__ pl10,
    const float* __restrict__ pr1,  const float* __restrict__ pr10,
    const int*   __restrict__ cam_idx,
    const int*   __restrict__ off_right,
    const int*   __restrict__ off_down,
    float* __restrict__ out)
{
    const int idx = blockIdx.x * blockDim.x + threadIdx.x;
    // grid is exact: NB*3*IMAGE*W4 = 602112 = 2352 * 256

    const int w4 = idx % W4;
    const int h  = (idx / W4) % IMAGE;
    const int c  = (idx / (W4 * IMAGE)) % 3;
    const int b  =  idx / (W4 * IMAGE * 3);

    const int ci  = cam_idx[b];
    const int orr = off_right[b];   // in [1, 30]
    const int od  = off_down[b];    // in [1, 30]

    const int off_l = 2 * PAD - orr;     // [30, 59]
    const int off_u = 2 * PAD - od;      // [30, 59]
    const int n10_l = off_l / 10;
    const int n10_u = off_u / 10;
    const int n1_r  = orr % 10;
    const int n1_d  = od % 10;

    int r = h - off_u;
    r = r < 0 ? 0 : (r > CROP - 1 ? CROP - 1 : r);
    const int hd = h - (IMAGE - od);

    // per-(ci, c) pad table bases (tiny, L1/L2 resident)
    const float* PU1  = pu1  + (ci * 3 + c) * IMAGE;       // [224]
    const float* PU10 = pu10 + (ci * 3 + c) * 10 * IMAGE;  // [10,224]
    const float* PD1  = pd1  + (ci * 3 + c) * IMAGE;
    const float* PD10 = pd10 + (ci * 3 + c) * 10 * IMAGE;
    const float* PL1  = pl1  + (ci * 3 + c) * CROP;        // [164]
    const float* PL10 = pl10 + (ci * 3 + c) * CROP * 10;   // [164,10]
    const float* PR1  = pr1  + (ci * 3 + c) * CROP;
    const float* PR10 = pr10 + (ci * 3 + c) * CROP * 10;

    // ------- build the 4 prompt scalars for this w-quad -------
    float p[4];
    #pragma unroll
    for (int k = 0; k < 4; k++) {
        const int w = w4 * 4 + k;
        float v;
        if (h < off_u) {
            v = (h < n10_u * 10) ? __ldg(&PU10[(h % 10) * IMAGE + w])
                                 : __ldg(&PU1[w]);
        } else if (h >= IMAGE - od) {
            if (hd < n1_d) {
                v = __ldg(&PD1[w]);
            } else {
                const int di = (hd - n1_d) % 10;
                v = __ldg(&PD10[di * IMAGE + w]);
            }
        } else {
            if (w < off_l) {
                v = (w < n10_l * 10) ? __ldg(&PL10[r * 10 + (w % 10)])
                                     : __ldg(&PL1[r]);
            } else if (w >= IMAGE - orr) {
                const int wd = w - (IMAGE - orr);
                if (wd < n1_r) {
                    v = __ldg(&PR1[r]);
                } else {
                    const int ri = (wd - n1_r) % 10;
                    v = __ldg(&PR10[r * 10 + ri]);
                }
            } else {
                v = 0.0f;
            }
        }
        p[k] = v;
    }

    const float px = p[0], py = p[1], pz = p[2], pw = p[3];

    // ------- stream x across T with float4 (evict-first, touch-once) -------
    // Identical structure to the best-measured kernel; only the cache policy
    // of the bulk stream changed (ldcs/stcs). ptxas batches the 4 loads per
    // unrolled group exactly as before (regs ~40).
    const size_t pstride = (size_t)(IMAGE * IMAGE) / 4;   // float4 per plane
    const size_t base = ((size_t)(b * 3 + c) * NT) * pstride
                      + (size_t)h * W4 + w4;
    const float4* __restrict__ xin  = reinterpret_cast<const float4*>(x)  + base;
    float4*       __restrict__ xout = reinterpret_cast<float4*>(out)      + base;

    #pragma unroll
    for (int t = 0; t < NT; t += 4) {
        float4 v0 = __ldcs(xin + (size_t)(t + 0) * pstride);
        float4 v1 = __ldcs(xin + (size_t)(t + 1) * pstride);
        float4 v2 = __ldcs(xin + (size_t)(t + 2) * pstride);
        float4 v3 = __ldcs(xin + (size_t)(t + 3) * pstride);

        v0.x += px; v0.y += py; v0.z += pz; v0.w += pw;
        v1.x += px; v1.y += py; v1.z += pz; v1.w += pw;
        v2.x += px; v2.y += py; v2.z += pz; v2.w += pw;
        v3.x += px; v3.y += py; v3.z += pz; v3.w += pw;

        __stcs(xout + (size_t)(t + 0) * pstride, v0);
        __stcs(xout + (size_t)(t + 1) * pstride, v1);
        __stcs(xout + (size_t)(t + 2) * pstride, v2);
        __stcs(xout + (size_t)(t + 3) * pstride, v3);
    }
}

extern "C" void kernel_launch(void* const* d_in, const int* in_sizes, int n_in,
                              void* d_out, int out_size) {
    const float* x    = (const float*)d_in[0];
    const float* pu1  = (const float*)d_in[1];
    const float* pu10 = (const float*)d_in[2];
    const float* pd1  = (const float*)d_in[3];
    const float* pd10 = (const float*)d_in[4];
    const float* pl1  = (const float*)d_in[5];
    const float* pl10 = (const float*)d_in[6];
    const float* pr1  = (const float*)d_in[7];
    const float* pr10 = (const float*)d_in[8];
    const int* cam_idx   = (const int*)d_in[9];
    const int* off_right = (const int*)d_in[10];
    const int* off_down  = (const int*)d_in[11];
    float* out = (float*)d_out;

    const int total   = NB * 3 * IMAGE * W4;   // 602112
    const int threads = 256;
    const int blocks  = total / threads;       // 2352 exact

    prompt_add_kernel<<<blocks, threads>>>(
        x, pu1, pu10, pd1, pd10, pl1, pl10, pr1, pr10,
        cam_idx, off_right, off_down, out);
}